// round 15
// baseline (speedup 1.0000x reference)
#include <cuda_runtime.h>
#include <cuda_fp16.h>
#include <math.h>

#define B_   32
#define CIN  256
#define COUT 512
#define A_   256
#define HW   4096

#define NT   64           // n-positions per CTA
#define C2   (CIN/2)      // packed-k rows (half2 along c)
#define NTL  (HW/NT)      // 64 n-tiles per batch
#define XSTR 72           // SX row stride (words): 72%32==8 -> conflict-free frags
#define WSTR 264          // SW row stride (words): 264%32==8
#define CH   32           // c2 rows per W chunk
#define NCH  (C2/CH)      // 4 chunks
#define SX_WORDS (C2*XSTR)            // 9216
#define SW_WORDS (2*CH*WSTR)          // 16896
#define DYN_WORDS (SX_WORDS + SW_WORDS)   // 26112 words = 104448 B

// ---- scratch ----
__device__ unsigned d_Wp[C2 * A_];        // packed half2 {Wx[a][2c2],Wx[a][2c2+1]} at [c2][a]
__device__ float d_gg[B_ * A_];           // g @ Wg^T + bg
__device__ float d_attraw[B_ * HW];       // pre-normalization scores
__device__ float d_Pp[B_ * NTL * CIN];    // pooling partials  sum_n x*attraw
__device__ float d_Sp[B_ * NTL * CIN];    // pooling partials  sum_n x
__device__ float d_mnp[B_ * NTL];         // per-tile min
__device__ float d_smp[B_ * NTL];         // per-tile sum

#define MMA_F16(c, a, bb)                                                       \
    asm volatile("mma.sync.aligned.m16n8k16.row.col.f32.f16.f16.f32 "           \
                 "{%0,%1,%2,%3},{%4,%5,%6,%7},{%8,%9},{%0,%1,%2,%3};"           \
                 : "+f"(c[0]), "+f"(c[1]), "+f"(c[2]), "+f"(c[3])               \
                 : "r"(a[0]), "r"(a[1]), "r"(a[2]), "r"(a[3]),                  \
                   "r"(bb[0]), "r"(bb[1]))

__device__ __forceinline__ unsigned pack_h2(float lo, float hi) {
    __half2 h = __floats2half2_rn(lo, hi);
    return *(unsigned*)&h;
}

// ============ K0: [transpose+pack Wx] (blocks 0-31) + [gg GEMV] (32-287) =====
__global__ void k_pre(const float* __restrict__ Wx,
                      const float* __restrict__ g,
                      const float* __restrict__ Wg,
                      const float* __restrict__ bg) {
    if (blockIdx.x < 32) {
        __shared__ float t[32][65];
        int cb = (blockIdx.x & 3) * 64, ab = (blockIdx.x >> 2) * 32;
        int tid = threadIdx.x;
        #pragma unroll
        for (int u = 0; u < 8; u++) {
            int idx = tid + u * 256;            // 2048 = 32*64
            int i = idx >> 6, j = idx & 63;
            t[i][j] = Wx[(size_t)(ab + i) * CIN + cb + j];
        }
        __syncthreads();
        #pragma unroll
        for (int u = 0; u < 4; u++) {
            int idx = tid + u * 256;            // 1024 = 32 c2 * 32 a
            int jj = idx >> 5, i = idx & 31;
            d_Wp[(size_t)(cb / 2 + jj) * A_ + ab + i] = pack_h2(t[i][2 * jj], t[i][2 * jj + 1]);
        }
    } else {
        __shared__ float gs[COUT];
        int idx = blockIdx.x - 32;              // 0..255
        int b = idx >> 3, a0 = (idx & 7) * 32;
        int tid = threadIdx.x;
        gs[tid]       = g[b * COUT + tid];
        gs[tid + 256] = g[b * COUT + tid + 256];
        __syncthreads();
        int warp = tid >> 5, lane = tid & 31;
        #pragma unroll
        for (int i = 0; i < 4; i++) {
            int a = a0 + warp * 4 + i;
            float s = 0.f;
            #pragma unroll
            for (int k = lane; k < COUT; k += 32)
                s += gs[k] * Wg[(size_t)a * COUT + k];
            #pragma unroll
            for (int o = 16; o; o >>= 1) s += __shfl_down_sync(0xffffffffu, s, o);
            if (!lane) d_gg[b * A_ + a] = s + bg[a];
        }
    }
}

// ---- issue one W chunk (32 c2 x 256 a words = 32 KB) via cp.async ----
__device__ __forceinline__ void issue_wchunk(unsigned* SWbuf, int ch, int tid) {
    const uint4* src = (const uint4*)(d_Wp + (size_t)ch * CH * A_);
    #pragma unroll
    for (int u = 0; u < 8; u++) {
        int v = tid + u * 256;                  // 2048 uint4
        int row = v >> 6, col4 = (v & 63) * 4;
        unsigned daddr = (unsigned)__cvta_generic_to_shared(&SWbuf[row * WSTR + col4]);
        asm volatile("cp.async.cg.shared.global [%0], [%1], 16;"
                     :: "r"(daddr), "l"(src + v));
    }
    asm volatile("cp.async.commit_group;");
}

// ============ K1: fp16 MMA GEMM (W streamed, x resident) + fused epilogue ====
// CTA = (n-tile of 64, batch). 8 warps as 2(n) x 4(a); warp tile 32n x 64a.
__global__ __launch_bounds__(256, 2) void k_main(
        const float* __restrict__ x,
        const float* __restrict__ bx,
        const float* __restrict__ Wf,
        const float* __restrict__ bf) {
    extern __shared__ unsigned smem[];
    unsigned* SX = smem;                  // [c2][n] half2 words, resident
    unsigned* SW = smem + SX_WORDS;       // 2 x [CH c2][a] half2 words
    __shared__ float s_gb[A_];
    __shared__ float s_wf[A_];
    __shared__ float s_red[NT * 5];
    __shared__ float s_att[NT];
    __shared__ float s_mn[2], s_sm[2];

    int b = blockIdx.y, nt = blockIdx.x, n0 = nt * NT;
    int tid = threadIdx.x, lane = tid & 31, w = tid >> 5;
    int t = lane & 3, gq = lane >> 2;
    int wa = w & 3, wn = w >> 2;

    // prefetch W chunks 0 and 1 (L2-hot) so they fly during the x load
    issue_wchunk(SW,             0, tid);
    issue_wchunk(SW + CH * WSTR, 1, tid);

    s_gb[tid] = d_gg[b * A_ + tid] + bx[tid];
    s_wf[tid] = Wf[tid];

    // ---- resident x tile [128 c2][64 n], f32 -> f16 pairs ----
    const float* xb = x + (size_t)b * CIN * HW + n0;
    #pragma unroll
    for (int u = 0; u < 8; u++) {
        int v = tid + u * 256;                // 2048 float4-pairs
        int c2 = v >> 4, n4 = (v & 15) * 4;
        const float4 r0 = *(const float4*)&xb[(size_t)(2 * c2) * HW + n4];
        const float4 r1 = *(const float4*)&xb[(size_t)(2 * c2 + 1) * HW + n4];
        uint4 o;
        o.x = pack_h2(r0.x, r1.x);
        o.y = pack_h2(r0.y, r1.y);
        o.z = pack_h2(r0.z, r1.z);
        o.w = pack_h2(r0.w, r1.w);
        *(uint4*)&SX[c2 * XSTR + n4] = o;
    }

    float acc[2][8][4];
    #pragma unroll
    for (int m = 0; m < 2; m++)
        #pragma unroll
        for (int j = 0; j < 8; j++)
            #pragma unroll
            for (int k = 0; k < 4; k++) acc[m][j][k] = 0.f;

    // ---- pipelined mainloop over 4 W chunks (4 ksteps each) ----
    #pragma unroll
    for (int ch = 0; ch < NCH; ch++) {
        if (ch < NCH - 1) asm volatile("cp.async.wait_group 1;");
        else              asm volatile("cp.async.wait_group 0;");
        __syncthreads();
        unsigned* SWb = SW + (ch & 1) * CH * WSTR;
        #pragma unroll
        for (int i = 0; i < 4; i++) {
            int kb = (ch * 4 + i) * 8;        // SX c2-row base (global)
            int kl = i * 8;                   // SW c2-row base (local)
            unsigned af[2][4], bfr[8][2];
            #pragma unroll
            for (int m = 0; m < 2; m++) {
                int nb = wn * 32 + m * 16 + gq;
                af[m][0] = SX[(kb + t) * XSTR + nb];
                af[m][1] = SX[(kb + t) * XSTR + nb + 8];
                af[m][2] = SX[(kb + t + 4) * XSTR + nb];
                af[m][3] = SX[(kb + t + 4) * XSTR + nb + 8];
            }
            #pragma unroll
            for (int j = 0; j < 8; j++) {
                int ab = wa * 64 + j * 8 + gq;
                bfr[j][0] = SWb[(kl + t) * WSTR + ab];
                bfr[j][1] = SWb[(kl + t + 4) * WSTR + ab];
            }
            #pragma unroll
            for (int m = 0; m < 2; m++)
                #pragma unroll
                for (int j = 0; j < 8; j++)
                    MMA_F16(acc[m][j], af[m], bfr[j]);
        }
        __syncthreads();
        if (ch + 2 < NCH)
            issue_wchunk(SW + (ch & 1) * CH * WSTR, ch + 2, tid);
    }

    // ---- epilogue 1: relu(acc + gg + bx) . Wf ----
    #pragma unroll
    for (int m = 0; m < 2; m++) {
        #pragma unroll
        for (int h = 0; h < 2; h++) {
            float s = 0.f;
            #pragma unroll
            for (int j = 0; j < 8; j++) {
                int a0 = wa * 64 + j * 8 + 2 * t;
                float v0 = acc[m][j][2 * h]     + s_gb[a0];
                float v1 = acc[m][j][2 * h + 1] + s_gb[a0 + 1];
                s += fmaxf(v0, 0.f) * s_wf[a0];
                s += fmaxf(v1, 0.f) * s_wf[a0 + 1];
            }
            s += __shfl_xor_sync(0xffffffffu, s, 1);
            s += __shfl_xor_sync(0xffffffffu, s, 2);
            if (t == 0)
                s_red[(wn * 32 + m * 16 + h * 8 + gq) * 5 + wa] = s;
        }
    }
    __syncthreads();
    if (tid < NT) {
        float s = s_red[tid * 5] + s_red[tid * 5 + 1] +
                  s_red[tid * 5 + 2] + s_red[tid * 5 + 3] + bf[0];
        s_att[tid] = s;
        d_attraw[b * HW + n0 + tid] = s;
        float mn = s, sm = s;
        #pragma unroll
        for (int o = 16; o; o >>= 1) {
            mn = fminf(mn, __shfl_xor_sync(0xffffffffu, mn, o));
            sm += __shfl_xor_sync(0xffffffffu, sm, o);
        }
        if (!lane) { s_mn[w] = mn; s_sm[w] = sm; }
    }
    __syncthreads();
    if (tid == 0) {
        d_mnp[b * NTL + nt] = fminf(s_mn[0], s_mn[1]);
        d_smp[b * NTL + nt] = s_sm[0] + s_sm[1];
    }

    // ---- pooling partials from resident x tile ----
    {
        int c = tid, c2 = c >> 1, hi = c & 1;
        float p = 0.f, sx = 0.f;
        #pragma unroll 8
        for (int n = 0; n < NT; n++) {
            __half2 h = *(__half2*)&SX[c2 * XSTR + n];
            float v = hi ? __high2float(h) : __low2float(h);
            p = fmaf(v, s_att[n], p);
            sx += v;
        }
        d_Pp[((size_t)b * NTL + nt) * CIN + c] = p;
        d_Sp[((size_t)b * NTL + nt) * CIN + c] = sx;
    }
}

// ============ K2: finalize — reduce stats, write att and out ============
__global__ void k_fin(float* __restrict__ out) {
    __shared__ float fin[2];
    int b = blockIdx.x, tid = threadIdx.x, lane = tid & 31;
    if (tid < 32) {
        float mn = fminf(d_mnp[b * NTL + lane], d_mnp[b * NTL + 32 + lane]);
        float sm = d_smp[b * NTL + lane] + d_smp[b * NTL + 32 + lane];
        #pragma unroll
        for (int o = 16; o; o >>= 1) {
            mn = fminf(mn, __shfl_down_sync(0xffffffffu, mn, o));
            sm += __shfl_down_sync(0xffffffffu, sm, o);
        }
        if (!lane) {
            fin[0] = mn;
            fin[1] = 1.f / (sm - (float)HW * mn);
        }
    }
    __syncthreads();
    float mn = fin[0], inv = fin[1];
    {
        int c = tid;
        float P = 0.f, S = 0.f;
        #pragma unroll 8
        for (int nt = 0; nt < NTL; nt++) {
            P += d_Pp[((size_t)b * NTL + nt) * CIN + c];
            S += d_Sp[((size_t)b * NTL + nt) * CIN + c];
        }
        out[b * CIN + c] = (P - mn * S) * inv;
    }
    float* ap = out + B_ * CIN + (size_t)b * HW;
    for (int n = tid; n < HW; n += 256)
        ap[n] = (d_attraw[b * HW + n] - mn) * inv;
}

// ============ launch ============
extern "C" void kernel_launch(void* const* d_in, const int* in_sizes, int n_in,
                              void* d_out, int out_size) {
    const float* x  = (const float*)d_in[0];
    const float* g  = (const float*)d_in[1];
    const float* Wg = (const float*)d_in[2];
    const float* bg = (const float*)d_in[3];
    const float* Wx = (const float*)d_in[4];
    const float* bx = (const float*)d_in[5];
    const float* Wf = (const float*)d_in[6];
    const float* bf = (const float*)d_in[7];
    float* out = (float*)d_out;   // [32*256] out ++ [32*4096] att

    cudaFuncSetAttribute(k_main, cudaFuncAttributeMaxDynamicSharedMemorySize,
                         DYN_WORDS * 4);

    k_pre <<<288, 256>>>(Wx, g, Wg, bg);
    k_main<<<dim3(NTL, B_), 256, DYN_WORDS * 4>>>(x, bx, Wf, bf);
    k_fin <<<B_, 256>>>(out);
}

// round 16
// speedup vs baseline: 1.4437x; 1.4437x over previous
#include <cuda_runtime.h>
#include <cuda_fp16.h>
#include <math.h>

#define B_   32
#define CIN  256
#define COUT 512
#define A_   256
#define HW   4096

#define NT   128          // n-positions per CTA
#define C2   (CIN/2)      // packed-k rows (half2 along c)
#define NTL  (HW/NT)      // 32 n-tiles per batch
#define XSTR 136          // SX row stride (words): %32==8 -> conflict-free frags
#define WSTR 264          // SW row stride (words): %32==8
#define WCH  32           // c2 rows per W chunk
#define NCH  (C2/WCH)     // 4 chunks
#define WBUF_WORDS (WCH*WSTR)          // 8448
#define XROWS 64          // c rows per x chunk (=32 c2)
#define XSTG_STR 132
#define XSTG_WORDS (XROWS*XSTG_STR)    // 8448
#define SX_WORDS (C2*XSTR)             // 17408
#define DYN_WORDS (SX_WORDS + 2*WBUF_WORDS + 2*XSTG_WORDS)  // 51200 = 204800 B

// ---- scratch ----
__device__ unsigned d_Wp[C2 * A_];        // packed half2 {Wx[a][2c2],Wx[a][2c2+1]} at [c2][a]
__device__ float d_gg[B_ * A_];
__device__ float d_attraw[B_ * HW];
__device__ float d_Pp[B_ * NTL * CIN];
__device__ float d_Sp[B_ * NTL * CIN];
__device__ float d_mnp[B_ * NTL];
__device__ float d_smp[B_ * NTL];

#define MMA_F16(c, a, bb)                                                       \
    asm volatile("mma.sync.aligned.m16n8k16.row.col.f32.f16.f16.f32 "           \
                 "{%0,%1,%2,%3},{%4,%5,%6,%7},{%8,%9},{%0,%1,%2,%3};"           \
                 : "+f"(c[0]), "+f"(c[1]), "+f"(c[2]), "+f"(c[3])               \
                 : "r"(a[0]), "r"(a[1]), "r"(a[2]), "r"(a[3]),                  \
                   "r"(bb[0]), "r"(bb[1]))

__device__ __forceinline__ unsigned pack_h2(float lo, float hi) {
    __half2 h = __floats2half2_rn(lo, hi);
    return *(unsigned*)&h;
}

// ============ K0: [transpose+pack Wx] (blocks 0-31) + [gg GEMV] (32-287) =====
__global__ void k_pre(const float* __restrict__ Wx,
                      const float* __restrict__ g,
                      const float* __restrict__ Wg,
                      const float* __restrict__ bg) {
    if (blockIdx.x < 32) {
        __shared__ float t[32][65];
        int cb = (blockIdx.x & 3) * 64, ab = (blockIdx.x >> 2) * 32;
        int tid = threadIdx.x;
        #pragma unroll
        for (int u = 0; u < 8; u++) {
            int idx = tid + u * 256;
            int i = idx >> 6, j = idx & 63;
            t[i][j] = Wx[(size_t)(ab + i) * CIN + cb + j];
        }
        __syncthreads();
        #pragma unroll
        for (int u = 0; u < 4; u++) {
            int idx = tid + u * 256;
            int jj = idx >> 5, i = idx & 31;
            d_Wp[(size_t)(cb / 2 + jj) * A_ + ab + i] = pack_h2(t[i][2 * jj], t[i][2 * jj + 1]);
        }
    } else {
        __shared__ float gs[COUT];
        int idx = blockIdx.x - 32;
        int b = idx >> 3, a0 = (idx & 7) * 32;
        int tid = threadIdx.x;
        gs[tid]       = g[b * COUT + tid];
        gs[tid + 256] = g[b * COUT + tid + 256];
        __syncthreads();
        int warp = tid >> 5, lane = tid & 31;
        #pragma unroll
        for (int i = 0; i < 4; i++) {
            int a = a0 + warp * 4 + i;
            float s = 0.f;
            #pragma unroll
            for (int k = lane; k < COUT; k += 32)
                s += gs[k] * Wg[(size_t)a * COUT + k];
            #pragma unroll
            for (int o = 16; o; o >>= 1) s += __shfl_down_sync(0xffffffffu, s, o);
            if (!lane) d_gg[b * A_ + a] = s + bg[a];
        }
    }
}

// ---- cp.async issuers (each followed by its own commit_group) ----
__device__ __forceinline__ void issue_w(unsigned* SWbuf, int ch, int tid) {
    const uint4* src = (const uint4*)(d_Wp + (size_t)ch * WCH * A_);
    #pragma unroll
    for (int u = 0; u < 8; u++) {
        int v = tid + u * 256;                  // 2048 uint4
        int row = v >> 6, col4 = (v & 63) * 4;
        unsigned daddr = (unsigned)__cvta_generic_to_shared(&SWbuf[row * WSTR + col4]);
        asm volatile("cp.async.cg.shared.global [%0], [%1], 16;"
                     :: "r"(daddr), "l"(src + v));
    }
    asm volatile("cp.async.commit_group;");
}
__device__ __forceinline__ void issue_x(float* XSbuf, int ch,
                                        const float* xb, int tid) {
    #pragma unroll
    for (int u = 0; u < 8; u++) {
        int v = tid + u * 256;                  // 2048 x 16B
        int row = v >> 5, s4 = (v & 31) * 4;
        unsigned daddr = (unsigned)__cvta_generic_to_shared(&XSbuf[row * XSTG_STR + s4]);
        asm volatile("cp.async.cg.shared.global [%0], [%1], 16;"
                     :: "r"(daddr), "l"(xb + (size_t)(ch * XROWS + row) * HW + s4));
    }
    asm volatile("cp.async.commit_group;");
}

// ============ K1: pipelined fp16 MMA GEMM + fused epilogue ============
// CTA = (n-tile of 128, batch). 8 warps as 2(n) x 4(a); warp tile 64n x 64a.
__global__ __launch_bounds__(256, 1) void k_main(
        const float* __restrict__ x,
        const float* __restrict__ bx,
        const float* __restrict__ Wf,
        const float* __restrict__ bf) {
    extern __shared__ unsigned smem[];
    unsigned* SX  = smem;                                   // [c2][n] f16, resident
    unsigned* SW0 = smem + SX_WORDS;                        // W chunk buffers
    unsigned* SW1 = SW0 + WBUF_WORDS;
    float* XS0 = (float*)(SW1 + WBUF_WORDS);                // x f32 staging
    float* XS1 = XS0 + XSTG_WORDS;
    __shared__ float s_gb[A_];
    __shared__ float s_wf[A_];
    __shared__ float s_red[NT * 5];
    __shared__ float s_att[NT];
    __shared__ float s_mn[4], s_sm[4];

    int b = blockIdx.y, nt = blockIdx.x, n0 = nt * NT;
    int tid = threadIdx.x, lane = tid & 31, w = tid >> 5;
    int t = lane & 3, gq = lane >> 2;
    int wa = w & 3, wn = w >> 2;

    const float* xb = x + (size_t)b * CIN * HW + n0;

    // prologue: 2 chunks of x and W in flight
    issue_x(XS0, 0, xb, tid);
    issue_w(SW0, 0, tid);
    issue_x(XS1, 1, xb, tid);
    issue_w(SW1, 1, tid);

    s_gb[tid] = d_gg[b * A_ + tid] + bx[tid];
    s_wf[tid] = Wf[tid];

    float acc[4][8][4];
    #pragma unroll
    for (int m = 0; m < 4; m++)
        #pragma unroll
        for (int j = 0; j < 8; j++)
            #pragma unroll
            for (int k = 0; k < 4; k++) acc[m][j][k] = 0.f;

    #pragma unroll
    for (int ch = 0; ch < NCH; ch++) {
        if (ch < NCH - 1) asm volatile("cp.async.wait_group 2;");
        else              asm volatile("cp.async.wait_group 0;");
        __syncthreads();

        // convert staged f32 chunk -> resident f16 SX rows [32ch, 32ch+32)
        float* XSb = (ch & 1) ? XS1 : XS0;
        #pragma unroll
        for (int u = 0; u < 16; u++) {
            int v = tid + u * 256;              // 4096 half2 words
            int c2l = v >> 7, n = v & 127;
            float f0 = XSb[(2 * c2l) * XSTG_STR + n];
            float f1 = XSb[(2 * c2l + 1) * XSTG_STR + n];
            SX[(ch * 32 + c2l) * XSTR + n] = pack_h2(f0, f1);
        }
        __syncthreads();                        // SX visible; XSb free
        if (ch + 2 < NCH) issue_x(XSb, ch + 2, xb, tid);

        unsigned* SWb = (ch & 1) ? SW1 : SW0;
        #pragma unroll
        for (int i = 0; i < 4; i++) {
            int kb = (ch * 4 + i) * 8;          // SX c2-row base
            int kl = i * 8;                     // SW local row base
            unsigned af[4][4], bfr[8][2];
            #pragma unroll
            for (int m = 0; m < 4; m++) {
                int nb = wn * 64 + m * 16 + gq;
                af[m][0] = SX[(kb + t) * XSTR + nb];
                af[m][1] = SX[(kb + t) * XSTR + nb + 8];
                af[m][2] = SX[(kb + t + 4) * XSTR + nb];
                af[m][3] = SX[(kb + t + 4) * XSTR + nb + 8];
            }
            #pragma unroll
            for (int j = 0; j < 8; j++) {
                int ab = wa * 64 + j * 8 + gq;
                bfr[j][0] = SWb[(kl + t) * WSTR + ab];
                bfr[j][1] = SWb[(kl + t + 4) * WSTR + ab];
            }
            #pragma unroll
            for (int m = 0; m < 4; m++)
                #pragma unroll
                for (int j = 0; j < 8; j++)
                    MMA_F16(acc[m][j], af[m], bfr[j]);
        }
        __syncthreads();                        // all warps done with SWb
        if (ch + 2 < NCH) issue_w(SWb, ch + 2, tid);
    }

    // ---- epilogue 1: relu(acc + gg + bx) . Wf ----
    #pragma unroll
    for (int m = 0; m < 4; m++) {
        #pragma unroll
        for (int h = 0; h < 2; h++) {
            float s = 0.f;
            #pragma unroll
            for (int j = 0; j < 8; j++) {
                int a0 = wa * 64 + j * 8 + 2 * t;
                float v0 = acc[m][j][2 * h]     + s_gb[a0];
                float v1 = acc[m][j][2 * h + 1] + s_gb[a0 + 1];
                s += fmaxf(v0, 0.f) * s_wf[a0];
                s += fmaxf(v1, 0.f) * s_wf[a0 + 1];
            }
            s += __shfl_xor_sync(0xffffffffu, s, 1);
            s += __shfl_xor_sync(0xffffffffu, s, 2);
            if (t == 0)
                s_red[(wn * 64 + m * 16 + h * 8 + gq) * 5 + wa] = s;
        }
    }
    __syncthreads();
    if (tid < NT) {
        float s = s_red[tid * 5] + s_red[tid * 5 + 1] +
                  s_red[tid * 5 + 2] + s_red[tid * 5 + 3] + bf[0];
        s_att[tid] = s;
        d_attraw[b * HW + n0 + tid] = s;
        float mn = s, sm = s;
        #pragma unroll
        for (int o = 16; o; o >>= 1) {
            mn = fminf(mn, __shfl_xor_sync(0xffffffffu, mn, o));
            sm += __shfl_xor_sync(0xffffffffu, sm, o);
        }
        if (!lane) { s_mn[w] = mn; s_sm[w] = sm; }
    }
    __syncthreads();
    if (tid == 0) {
        float mn = fminf(fminf(s_mn[0], s_mn[1]), fminf(s_mn[2], s_mn[3]));
        d_mnp[b * NTL + nt] = mn;
        d_smp[b * NTL + nt] = s_sm[0] + s_sm[1] + s_sm[2] + s_sm[3];
    }

    // ---- pooling partials from resident f16 x tile ----
    {
        int c = tid, c2 = c >> 1, hi = c & 1;
        float p = 0.f, sx = 0.f;
        #pragma unroll 8
        for (int n = 0; n < NT; n++) {
            __half2 h = *(__half2*)&SX[c2 * XSTR + n];
            float v = hi ? __high2float(h) : __low2float(h);
            p = fmaf(v, s_att[n], p);
            sx += v;
        }
        d_Pp[((size_t)b * NTL + nt) * CIN + c] = p;
        d_Sp[((size_t)b * NTL + nt) * CIN + c] = sx;
    }
}

// ============ K2: finalize — reduce stats, write att and out ============
__global__ void k_fin(float* __restrict__ out) {
    __shared__ float fin[2];
    int b = blockIdx.x, tid = threadIdx.x, lane = tid & 31;
    if (tid < 32) {
        float mn = d_mnp[b * NTL + lane];
        float sm = d_smp[b * NTL + lane];
        #pragma unroll
        for (int o = 16; o; o >>= 1) {
            mn = fminf(mn, __shfl_down_sync(0xffffffffu, mn, o));
            sm += __shfl_down_sync(0xffffffffu, sm, o);
        }
        if (!lane) {
            fin[0] = mn;
            fin[1] = 1.f / (sm - (float)HW * mn);
        }
    }
    __syncthreads();
    float mn = fin[0], inv = fin[1];
    {
        int c = tid;
        float P = 0.f, S = 0.f;
        #pragma unroll
        for (int nt = 0; nt < NTL; nt++) {
            P += d_Pp[((size_t)b * NTL + nt) * CIN + c];
            S += d_Sp[((size_t)b * NTL + nt) * CIN + c];
        }
        out[b * CIN + c] = (P - mn * S) * inv;
    }
    float* ap = out + B_ * CIN + (size_t)b * HW;
    for (int n = tid; n < HW; n += 256)
        ap[n] = (d_attraw[b * HW + n] - mn) * inv;
}

// ============ launch ============
extern "C" void kernel_launch(void* const* d_in, const int* in_sizes, int n_in,
                              void* d_out, int out_size) {
    const float* x  = (const float*)d_in[0];
    const float* g  = (const float*)d_in[1];
    const float* Wg = (const float*)d_in[2];
    const float* bg = (const float*)d_in[3];
    const float* Wx = (const float*)d_in[4];
    const float* bx = (const float*)d_in[5];
    const float* Wf = (const float*)d_in[6];
    const float* bf = (const float*)d_in[7];
    float* out = (float*)d_out;   // [32*256] out ++ [32*4096] att

    cudaFuncSetAttribute(k_main, cudaFuncAttributeMaxDynamicSharedMemorySize,
                         DYN_WORDS * 4);

    k_pre <<<288, 256>>>(Wx, g, Wg, bg);
    k_main<<<dim3(NTL, B_), 256, DYN_WORDS * 4>>>(x, bx, Wf, bf);
    k_fin <<<B_, 256>>>(out);
}